// round 16
// baseline (speedup 1.0000x reference)
#include <cuda_runtime.h>

#define AR_P 64
#define AR_T 65536
#define CHUNK_L 8192
#define N_CHUNKS 8   // AR_T / CHUNK_L

__device__ __align__(16) float g_hpad[AR_P + CHUNK_L];   // h with 64 leading zeros
__device__ __align__(16) float g_H[CHUNK_L];             // inclusive prefix sum of h
__device__ float g_phi[N_CHUNKS][AR_P];                  // per-chunk boundary projections
__device__ __align__(16) float g_means[AR_T];

typedef unsigned long long u64;

// ---- packed f32x2 helpers (Blackwell FFMA2) --------------------------------
__device__ __forceinline__ void fma2(u64& d, u64 a, u64 b) {
    asm("fma.rn.f32x2 %0, %1, %2, %0;" : "+l"(d) : "l"(a), "l"(b));
}
// O = {hi(eprev), lo(ecur)}  (first float = low 32 bits)
__device__ __forceinline__ u64 pack_odd(u64 eprev, u64 ecur) {
    u64 r;
    asm("mov.b64 %0, {%1, %2};" : "=l"(r)
        : "r"((unsigned)(eprev >> 32)), "r"((unsigned)ecur));
    return r;
}

// ---------------------------------------------------------------------------
// Conflict-free 64-tap convolution for 4 consecutive outputs (smem source).
// out[r] = sum_{i=0}^{63} src[base0 + r - i] * phi[i], r = 0..3.
// ---------------------------------------------------------------------------
__device__ __forceinline__ void conv4_f4(const float* __restrict__ src, int base0,
                                         const float* __restrict__ phi,
                                         float& a0, float& a1, float& a2, float& a3) {
    const float4 va = *reinterpret_cast<const float4*>(&src[base0]);
    const float4 vb = *reinterpret_cast<const float4*>(&src[base0 - 4]);
    float v0 = vb.x, v1 = vb.y, v2 = vb.z, v3 = vb.w;
    float v4 = va.x, v5 = va.y, v6 = va.z, v7 = va.w;
    a0 = 0.f; a1 = 0.f; a2 = 0.f; a3 = 0.f;
    #pragma unroll
    for (int i4 = 0; i4 < 16; i4++) {
        if (i4 > 0) {
            v4 = v0; v5 = v1; v6 = v2; v7 = v3;
            const float4 nv = *reinterpret_cast<const float4*>(&src[base0 - 4 - 4 * i4]);
            v0 = nv.x; v1 = nv.y; v2 = nv.z; v3 = nv.w;
        }
        const float4 p = *reinterpret_cast<const float4*>(&phi[4 * i4]);
        a0 += v4 * p.x; a1 += v5 * p.x; a2 += v6 * p.x; a3 += v7 * p.x;
        a0 += v3 * p.y; a1 += v4 * p.y; a2 += v5 * p.y; a3 += v6 * p.y;
        a0 += v2 * p.z; a1 += v3 * p.z; a2 += v4 * p.z; a3 += v5 * p.z;
        a0 += v1 * p.w; a1 += v2 * p.w; a2 += v3 * p.w; a3 += v4 * p.w;
    }
}

// ---------------------------------------------------------------------------
// Packed 64-tap convolution for 8 consecutive outputs (base0 % 8 == 0).
// out[r] = sum_i src[base0 + r - i] * phi[i], r = 0..7.
// E_k = {src[base0+2k], src[base0+2k+1]} packed pairs; phid[i] = {phi_i, phi_i}.
// ---------------------------------------------------------------------------
__device__ __forceinline__ void conv8_f32x2(const float* __restrict__ src, int base0,
                                            const u64* __restrict__ phid,
                                            float4& lo4, float4& hi4) {
    u64 A0 = 0, A1 = 0, A2 = 0, A3 = 0;
    const ulonglong2* base = reinterpret_cast<const ulonglong2*>(&src[base0]);
    ulonglong2 q1 = base[1];    // {E2, E3}
    ulonglong2 q0 = base[0];    // {E0, E1}
    ulonglong2 qm = base[-1];   // {E-2, E-1}
    u64 e5 = q1.y, e4 = q1.x, e3 = q0.y, e2 = q0.x, e1 = qm.y, e0 = qm.x;
    #pragma unroll
    for (int g = 0; g < 16; g++) {
        const u64 p0 = phid[4 * g + 0], p1 = phid[4 * g + 1];
        const u64 p2 = phid[4 * g + 2], p3 = phid[4 * g + 3];
        // tap 4g (even, t=2g): A_p += E_{p-2g} * dup(phi)
        fma2(A3, e5, p0); fma2(A2, e4, p0); fma2(A1, e3, p0); fma2(A0, e2, p0);
        const u64 o54 = pack_odd(e4, e5);
        const u64 o43 = pack_odd(e3, e4);
        const u64 o32 = pack_odd(e2, e3);
        const u64 o21 = pack_odd(e1, e2);
        // tap 4g+1 (odd)
        fma2(A3, o54, p1); fma2(A2, o43, p1); fma2(A1, o32, p1); fma2(A0, o21, p1);
        // tap 4g+2 (even, t=2g+1)
        fma2(A3, e4, p2); fma2(A2, e3, p2); fma2(A1, e2, p2); fma2(A0, e1, p2);
        const u64 o10 = pack_odd(e0, e1);
        // tap 4g+3 (odd)
        fma2(A3, o43, p3); fma2(A2, o32, p3); fma2(A1, o21, p3); fma2(A0, o10, p3);
        if (g < 15) {
            const ulonglong2 nq = base[-2 - g];   // {E_{-4-2g}, E_{-3-2g}}
            e5 = e3; e4 = e2; e3 = e1; e2 = e0; e1 = nq.y; e0 = nq.x;
        }
    }
    lo4 = make_float4(__uint_as_float((unsigned)A0), __uint_as_float((unsigned)(A0 >> 32)),
                      __uint_as_float((unsigned)A1), __uint_as_float((unsigned)(A1 >> 32)));
    hi4 = make_float4(__uint_as_float((unsigned)A2), __uint_as_float((unsigned)(A2 >> 32)),
                      __uint_as_float((unsigned)A3), __uint_as_float((unsigned)(A3 >> 32)));
}

// returns sum_{j=0..63} A[abase + j] * B[btop - j]
__device__ __forceinline__ float dot64_4acc_fwd_rev(const float* __restrict__ A, int abase,
                                                    const float* __restrict__ B, int btop) {
    float s0 = 0.f, s1 = 0.f, s2 = 0.f, s3 = 0.f;
    #pragma unroll
    for (int j = 0; j < AR_P; j += 4) {
        s0 += A[abase + j + 0] * B[btop - j - 0];
        s1 += A[abase + j + 1] * B[btop - j - 1];
        s2 += A[abase + j + 2] * B[btop - j - 2];
        s3 += A[abase + j + 3] * B[btop - j - 3];
    }
    return (s0 + s1) + (s2 + s3);
}

// returns sum_{j=0..63} A[j] * B[j]
__device__ __forceinline__ float dot64_4acc_fwd_fwd(const float* __restrict__ A,
                                                    const float* __restrict__ B) {
    float s0 = 0.f, s1 = 0.f, s2 = 0.f, s3 = 0.f;
    #pragma unroll
    for (int j = 0; j < AR_P; j += 4) {
        s0 += A[j + 0] * B[j + 0];
        s1 += A[j + 1] * B[j + 1];
        s2 += A[j + 2] * B[j + 2];
        s3 += A[j + 3] * B[j + 3];
    }
    return (s0 + s1) + (s2 + s3);
}

// ---------------------------------------------------------------------------
// Kernel 1 (single block, 1024 thr): h by wavefront + doubling (packed FFMA2
// for big levels), prefix sum -> g_H, Hankel hop, parallel phi_c.
// ---------------------------------------------------------------------------
__global__ __launch_bounds__(1024) void k1_prep(const float* __restrict__ params,
                                                const float* __restrict__ bias) {
    __shared__ __align__(16) float Pp[2 * AR_P];                    // params + 64 zeros
    __shared__ __align__(16) float hs[AR_P + CHUNK_L + AR_P];       // pad + h[0..8256)
    __shared__ __align__(16) float phi[AR_P];
    __shared__ __align__(16) u64 phid[AR_P];                        // dup'd phi pairs
    __shared__ float red[32];
    __shared__ float Htail[AR_P];                                   // H[8191-j]
    __shared__ float scur[AR_P];
    __shared__ float sst[N_CHUNKS][AR_P];

    const int tid = threadIdx.x;
    const int lane = tid & 31;
    const float bv = bias[0];

    if (tid < 2 * AR_P) Pp[tid] = (tid < AR_P) ? params[tid] : 0.0f;
    if (tid < AR_P) hs[tid] = 0.0f;          // left zero pad h_{-64..-1}
    __syncthreads();

    // ---- wavefront: h[0..32) in warp 0 ----
    if (tid < 32) {
        float val = (lane == 0) ? 1.0f : 0.0f;   // h_0 = 1
        float acc = 0.0f;
        #pragma unroll
        for (int r = 0; r < 31; r++) {
            const float hr = __shfl_sync(0xffffffffu, val, r);
            if (lane > r) acc = fmaf(Pp[lane - 1 - r], hr, acc);
            if (lane == r + 1) val = acc;
        }
        hs[AR_P + lane] = val;
        __syncwarp();

        // ---- level n = 32 ----
        {
            const int n = 32;
            #pragma unroll 2
            for (int i = lane; i < AR_P; i += 32)
                phi[i] = dot64_4acc_fwd_rev(Pp, i, hs, AR_P + n - 1);
            __syncwarp();
            hs[AR_P + n + lane] = dot64_4acc_fwd_rev(phi, 0, hs, AR_P + lane);
            __syncwarp();
        }

        // ---- levels n = 64, 128 : conv4, warp 0 ----
        for (int n = AR_P; n < 256; n <<= 1) {
            #pragma unroll 2
            for (int i = lane; i < AR_P; i += 32)
                phi[i] = dot64_4acc_fwd_rev(Pp, i, hs, AR_P + n - 1);
            __syncwarp();
            const int nt = n >> 2;
            for (int t = lane; t < nt; t += 32) {
                float a0, a1, a2, a3;
                conv4_f4(hs, AR_P + 4 * t, phi, a0, a1, a2, a3);
                *reinterpret_cast<float4*>(&hs[AR_P + n + 4 * t]) =
                    make_float4(a0, a1, a2, a3);
            }
            __syncwarp();
        }
    }
    __syncthreads();

    // ---- levels n = 256 .. 4096 : full block ----
    for (int n = 256; n < CHUNK_L; n <<= 1) {
        // phi: 4 threads per entry + shfl reduce
        if (tid < 256) {
            const int i = tid >> 2, q = tid & 3;
            float acc = 0.0f;
            #pragma unroll
            for (int j = 0; j < 16; j++) {
                const int jj = q * 16 + j;
                acc += Pp[i + jj] * hs[AR_P + n - 1 - jj];
            }
            acc += __shfl_xor_sync(0xffffffffu, acc, 1);
            acc += __shfl_xor_sync(0xffffffffu, acc, 2);
            if (q == 0) {
                phi[i] = acc;
                const unsigned u = __float_as_uint(acc);
                phid[i] = ((u64)u << 32) | u;
            }
        }
        __syncthreads();
        if (n == 256) {
            if (tid < (n >> 2)) {
                float a0, a1, a2, a3;
                conv4_f4(hs, AR_P + 4 * tid, phi, a0, a1, a2, a3);
                *reinterpret_cast<float4*>(&hs[AR_P + n + 4 * tid]) =
                    make_float4(a0, a1, a2, a3);
            }
        } else {
            const int nt8 = n >> 3;
            if (tid < nt8) {
                float4 lo4, hi4;
                conv8_f32x2(hs, AR_P + 8 * tid, phid, lo4, hi4);
                *reinterpret_cast<float4*>(&hs[AR_P + n + 8 * tid]) = lo4;
                *reinterpret_cast<float4*>(&hs[AR_P + n + 8 * tid + 4]) = hi4;
            }
        }
        __syncthreads();
    }

    // ---- extension: h[8192 .. 8256) (needed by the Hankel hop) ----
    if (tid < AR_P)
        phi[tid] = dot64_4acc_fwd_rev(Pp, tid, hs, AR_P + CHUNK_L - 1);
    __syncthreads();
    if (tid < AR_P)
        hs[AR_P + CHUNK_L + tid] = dot64_4acc_fwd_rev(phi, 0, hs, AR_P + tid);
    __syncthreads();

    // ---- write padded h[-64..8192) to global ----
    {
        const float4* s4 = reinterpret_cast<const float4*>(hs);
        float4* d4 = reinterpret_cast<float4*>(g_hpad);
        for (int q = tid; q < (AR_P + CHUNK_L) / 4; q += 1024) d4[q] = s4[q];
    }

    // ---- inclusive prefix sum of h -> g_H; stage H tail ----
    float v[8];
    float s = 0.0f;
    #pragma unroll
    for (int k = 0; k < 8; k++) { v[k] = hs[AR_P + tid * 8 + k]; s += v[k]; }
    float ss = s;
    #pragma unroll
    for (int o = 1; o < 32; o <<= 1) {
        const float t2 = __shfl_up_sync(0xffffffffu, ss, o);
        if (lane >= o) ss += t2;
    }
    if (lane == 31) red[tid >> 5] = ss;
    __syncthreads();
    if (tid < 32) {
        float ws = red[tid];
        #pragma unroll
        for (int o = 1; o < 32; o <<= 1) {
            const float t2 = __shfl_up_sync(0xffffffffu, ws, o);
            if (tid >= o) ws += t2;
        }
        red[tid] = ws;
    }
    __syncthreads();
    float run = (ss - s) + ((tid >= 32) ? red[(tid >> 5) - 1] : 0.0f);
    #pragma unroll
    for (int k = 0; k < 8; k++) {
        run += v[k];
        const int idx = tid * 8 + k;
        g_H[idx] = run;
        if (idx >= CHUNK_L - AR_P) Htail[CHUNK_L - 1 - idx] = run;  // H[8191-j]
    }

    // ---- Hankel hop: s_{c+1}[j] = sum_{j'} h[L-j+j'] s_c[j'] + bv*H[L-1-j] ----
    if (tid < AR_P) { scur[tid] = 0.0f; sst[0][tid] = 0.0f; }
    __syncthreads();
    for (int c = 1; c < N_CHUNKS; c++) {
        float ns = 0.0f;
        if (tid < AR_P)
            ns = dot64_4acc_fwd_fwd(scur, &hs[AR_P + CHUNK_L - tid]) + bv * Htail[tid];
        __syncthreads();
        if (tid < AR_P) { scur[tid] = ns; sst[c][tid] = ns; }
        __syncthreads();
    }

    // ---- ALL phi_c in parallel ----
    if (tid < N_CHUNKS * AR_P) {
        const int c = tid >> 6;
        const int i = tid & (AR_P - 1);
        g_phi[c][i] = (c == 0) ? 0.0f : dot64_4acc_fwd_fwd(&Pp[i], sst[c]);
    }
}

// ---------------------------------------------------------------------------
// Kernel 2: fill all means. grid = 64 blocks x 256 threads.
// ---------------------------------------------------------------------------
__global__ __launch_bounds__(256) void k2_means(const float* __restrict__ bias) {
    const int c = blockIdx.x >> 3;
    const int part = blockIdx.x & 7;
    const int m0base = part * 1024;

    __shared__ __align__(16) float phi[AR_P];
    __shared__ __align__(16) float hw[1088];

    const int tid = threadIdx.x;
    if (tid < AR_P) phi[tid] = g_phi[c][tid];
    {
        const float4* g4 = reinterpret_cast<const float4*>(&g_hpad[m0base]);
        float4* s4 = reinterpret_cast<float4*>(hw);
        for (int q = tid; q < 1088 / 4; q += 256) s4[q] = g4[q];
    }
    __syncthreads();

    const float bv = bias[0];
    const int d = tid * 4;
    float a0, a1, a2, a3;
    conv4_f4(hw, 64 + d, phi, a0, a1, a2, a3);

    const int m = m0base + d;
    const float4 Hv = *reinterpret_cast<const float4*>(&g_H[m]);
    float4 r;
    r.x = fmaf(bv, Hv.x, a0);
    r.y = fmaf(bv, Hv.y, a1);
    r.z = fmaf(bv, Hv.z, a2);
    r.w = fmaf(bv, Hv.w, a3);
    *reinterpret_cast<float4*>(&g_means[c * CHUNK_L + m]) = r;
}

// ---------------------------------------------------------------------------
// Kernel 3: out[b,t] = means[t] + 0.3*noise[b,t]  (float4 streaming)
// ---------------------------------------------------------------------------
__global__ __launch_bounds__(256) void k3_out(const float4* __restrict__ noise,
                                              float4* __restrict__ out) {
    const int idx = blockIdx.x * 256 + threadIdx.x;
    const int t4 = idx & (AR_T / 4 - 1);
    const float4 nz = __ldcs(&noise[idx]);
    const float4 mn = reinterpret_cast<const float4*>(g_means)[t4];
    float4 r;
    r.x = fmaf(0.3f, nz.x, mn.x);
    r.y = fmaf(0.3f, nz.y, mn.y);
    r.z = fmaf(0.3f, nz.z, mn.z);
    r.w = fmaf(0.3f, nz.w, mn.w);
    __stcs(&out[idx], r);
}

extern "C" void kernel_launch(void* const* d_in, const int* in_sizes, int n_in,
                              void* d_out, int out_size) {
    const float* params = nullptr;
    const float* bias   = nullptr;
    const float* noise  = nullptr;
    for (int i = 0; i < n_in; i++) {
        if (in_sizes[i] == AR_P)      params = (const float*)d_in[i];
        else if (in_sizes[i] == 1)    bias   = (const float*)d_in[i];
        else                          noise  = (const float*)d_in[i];
    }

    k1_prep<<<1, 1024>>>(params, bias);
    k2_means<<<N_CHUNKS * 8, 256>>>(bias);

    const int total4 = out_size / 4;          // 4,194,304 float4s
    k3_out<<<total4 / 256, 256>>>((const float4*)noise, (float4*)d_out);
}

// round 17
// speedup vs baseline: 1.1569x; 1.1569x over previous
#include <cuda_runtime.h>

#define AR_P 64
#define AR_T 65536
#define CHUNK_L 8192
#define N_CHUNKS 8   // AR_T / CHUNK_L

#define K1_GRID 64   // CTA 0: prep work; CTAs 1..63: L2 prefetch of noise

__device__ __align__(16) float g_hpad[AR_P + CHUNK_L];   // h with 64 leading zeros
__device__ __align__(16) float g_H[CHUNK_L];             // inclusive prefix sum of h
__device__ float g_phi[N_CHUNKS][AR_P];                  // per-chunk boundary projections
__device__ __align__(16) float g_means[AR_T];
__device__ float g_sink;                                 // DCE defeat for prefetch

// ---------------------------------------------------------------------------
// Conflict-free 64-tap convolution for 4 consecutive outputs (smem source).
// out[r] = sum_{i=0}^{63} src[base0 + r - i] * phi[i], r = 0..3.
// ---------------------------------------------------------------------------
__device__ __forceinline__ void conv4_f4(const float* __restrict__ src, int base0,
                                         const float* __restrict__ phi,
                                         float& a0, float& a1, float& a2, float& a3) {
    const float4 va = *reinterpret_cast<const float4*>(&src[base0]);
    const float4 vb = *reinterpret_cast<const float4*>(&src[base0 - 4]);
    float v0 = vb.x, v1 = vb.y, v2 = vb.z, v3 = vb.w;
    float v4 = va.x, v5 = va.y, v6 = va.z, v7 = va.w;
    a0 = 0.f; a1 = 0.f; a2 = 0.f; a3 = 0.f;
    #pragma unroll
    for (int i4 = 0; i4 < 16; i4++) {
        if (i4 > 0) {
            v4 = v0; v5 = v1; v6 = v2; v7 = v3;
            const float4 nv = *reinterpret_cast<const float4*>(&src[base0 - 4 - 4 * i4]);
            v0 = nv.x; v1 = nv.y; v2 = nv.z; v3 = nv.w;
        }
        const float4 p = *reinterpret_cast<const float4*>(&phi[4 * i4]);
        a0 += v4 * p.x; a1 += v5 * p.x; a2 += v6 * p.x; a3 += v7 * p.x;
        a0 += v3 * p.y; a1 += v4 * p.y; a2 += v5 * p.y; a3 += v6 * p.y;
        a0 += v2 * p.z; a1 += v3 * p.z; a2 += v4 * p.z; a3 += v5 * p.z;
        a0 += v1 * p.w; a1 += v2 * p.w; a2 += v3 * p.w; a3 += v4 * p.w;
    }
}

// returns sum_{j=0..63} A[abase + j] * B[btop - j]
__device__ __forceinline__ float dot64_4acc_fwd_rev(const float* __restrict__ A, int abase,
                                                    const float* __restrict__ B, int btop) {
    float s0 = 0.f, s1 = 0.f, s2 = 0.f, s3 = 0.f;
    #pragma unroll
    for (int j = 0; j < AR_P; j += 4) {
        s0 += A[abase + j + 0] * B[btop - j - 0];
        s1 += A[abase + j + 1] * B[btop - j - 1];
        s2 += A[abase + j + 2] * B[btop - j - 2];
        s3 += A[abase + j + 3] * B[btop - j - 3];
    }
    return (s0 + s1) + (s2 + s3);
}

// returns sum_{j=0..63} A[j] * B[j]
__device__ __forceinline__ float dot64_4acc_fwd_fwd(const float* __restrict__ A,
                                                    const float* __restrict__ B) {
    float s0 = 0.f, s1 = 0.f, s2 = 0.f, s3 = 0.f;
    #pragma unroll
    for (int j = 0; j < AR_P; j += 4) {
        s0 += A[j + 0] * B[j + 0];
        s1 += A[j + 1] * B[j + 1];
        s2 += A[j + 2] * B[j + 2];
        s3 += A[j + 3] * B[j + 3];
    }
    return (s0 + s1) + (s2 + s3);
}

// ---------------------------------------------------------------------------
// Kernel 1 (grid = 64 x 1024):
//   CTA 0  : h by wavefront + doubling, prefix sum -> g_H, Hankel hop, phi_c.
//   CTA >0 : prefetch the 64MB noise buffer into L2 (overlapped with CTA 0).
// ---------------------------------------------------------------------------
__global__ __launch_bounds__(1024) void k1_prep(const float* __restrict__ params,
                                                const float* __restrict__ bias,
                                                const float4* __restrict__ noise) {
    const int tid = threadIdx.x;
    const int blk = blockIdx.x;

    // ============ prefetch CTAs: warm L2 with noise ============
    if (blk > 0) {
        const int total4 = (AR_T / 4) * 256;          // 4,194,304 float4
        float acc = 0.0f;
        for (int q = (blk - 1) * 1024 + tid; q < total4; q += (K1_GRID - 1) * 1024) {
            const float4 v = __ldcg(&noise[q]);       // L2-level load
            acc += (v.x + v.y) + (v.z + v.w);
        }
        g_sink = acc;                                  // defeat DCE (never read)
        return;
    }

    // ============ CTA 0: the R15 prep pipeline ============
    __shared__ __align__(16) float Pp[2 * AR_P];                    // params + 64 zeros
    __shared__ __align__(16) float hs[AR_P + CHUNK_L + AR_P];       // pad + h[0..8256)
    __shared__ __align__(16) float phi[AR_P];
    __shared__ float red[32];
    __shared__ float Htail[AR_P];                                   // H[8191-j]
    __shared__ float scur[AR_P];
    __shared__ float sst[N_CHUNKS][AR_P];

    const int lane = tid & 31;
    const float bv = bias[0];

    if (tid < 2 * AR_P) Pp[tid] = (tid < AR_P) ? params[tid] : 0.0f;
    if (tid < AR_P) hs[tid] = 0.0f;          // left zero pad h_{-64..-1}
    __syncthreads();

    // ---- wavefront: h[0..32) in warp 0 (serial chain via shfl) ----
    if (tid < 32) {
        float val = (lane == 0) ? 1.0f : 0.0f;   // h_0 = 1
        float acc = 0.0f;
        #pragma unroll
        for (int r = 0; r < 31; r++) {
            const float hr = __shfl_sync(0xffffffffu, val, r);
            if (lane > r) acc = fmaf(Pp[lane - 1 - r], hr, acc);
            if (lane == r + 1) val = acc;
        }
        hs[AR_P + lane] = val;
        __syncwarp();

        // ---- level n = 32 : scalar, warp 0 ----
        {
            const int n = 32;
            #pragma unroll 2
            for (int i = lane; i < AR_P; i += 32)
                phi[i] = dot64_4acc_fwd_rev(Pp, i, hs, AR_P + n - 1);
            __syncwarp();
            hs[AR_P + n + lane] = dot64_4acc_fwd_rev(phi, 0, hs, AR_P + lane);
            __syncwarp();
        }

        // ---- levels n = 64, 128 : float4 path, still warp 0 ----
        for (int n = AR_P; n < 256; n <<= 1) {
            #pragma unroll 2
            for (int i = lane; i < AR_P; i += 32)
                phi[i] = dot64_4acc_fwd_rev(Pp, i, hs, AR_P + n - 1);
            __syncwarp();
            const int nt = n >> 2;
            for (int t = lane; t < nt; t += 32) {
                float a0, a1, a2, a3;
                conv4_f4(hs, AR_P + 4 * t, phi, a0, a1, a2, a3);
                *reinterpret_cast<float4*>(&hs[AR_P + n + 4 * t]) =
                    make_float4(a0, a1, a2, a3);
            }
            __syncwarp();
        }
    }
    __syncthreads();

    // ---- levels n = 256 .. 4096 : full block ----
    for (int n = 256; n < CHUNK_L; n <<= 1) {
        if (tid < AR_P)
            phi[tid] = dot64_4acc_fwd_rev(Pp, tid, hs, AR_P + n - 1);
        __syncthreads();
        const int nt = n >> 2;
        if (tid < nt) {
            float a0, a1, a2, a3;
            conv4_f4(hs, AR_P + 4 * tid, phi, a0, a1, a2, a3);
            *reinterpret_cast<float4*>(&hs[AR_P + n + 4 * tid]) =
                make_float4(a0, a1, a2, a3);
        }
        __syncthreads();
    }

    // ---- extension: h[8192 .. 8256) (needed by the Hankel hop) ----
    if (tid < AR_P)
        phi[tid] = dot64_4acc_fwd_rev(Pp, tid, hs, AR_P + CHUNK_L - 1);
    __syncthreads();
    if (tid < AR_P)
        hs[AR_P + CHUNK_L + tid] = dot64_4acc_fwd_rev(phi, 0, hs, AR_P + tid);
    __syncthreads();

    // ---- write padded h[-64..8192) to global (float4) ----
    {
        const float4* s4 = reinterpret_cast<const float4*>(hs);
        float4* d4 = reinterpret_cast<float4*>(g_hpad);
        for (int q = tid; q < (AR_P + CHUNK_L) / 4; q += 1024) d4[q] = s4[q];
    }

    // ---- inclusive prefix sum of h -> g_H (8 elems/thread); stage H tail ----
    float v[8];
    float s = 0.0f;
    #pragma unroll
    for (int k = 0; k < 8; k++) { v[k] = hs[AR_P + tid * 8 + k]; s += v[k]; }
    float ss = s;
    #pragma unroll
    for (int o = 1; o < 32; o <<= 1) {
        const float t2 = __shfl_up_sync(0xffffffffu, ss, o);
        if (lane >= o) ss += t2;
    }
    if (lane == 31) red[tid >> 5] = ss;
    __syncthreads();
    if (tid < 32) {
        float ws = red[tid];
        #pragma unroll
        for (int o = 1; o < 32; o <<= 1) {
            const float t2 = __shfl_up_sync(0xffffffffu, ws, o);
            if (tid >= o) ws += t2;
        }
        red[tid] = ws;
    }
    __syncthreads();
    float run = (ss - s) + ((tid >= 32) ? red[(tid >> 5) - 1] : 0.0f);
    #pragma unroll
    for (int k = 0; k < 8; k++) {
        run += v[k];
        const int idx = tid * 8 + k;
        g_H[idx] = run;
        if (idx >= CHUNK_L - AR_P) Htail[CHUNK_L - 1 - idx] = run;  // H[8191-j]
    }

    // ---- Hankel hop: s_{c+1}[j] = sum_{j'} h[L-j+j'] s_c[j'] + bv*H[L-1-j] ----
    if (tid < AR_P) { scur[tid] = 0.0f; sst[0][tid] = 0.0f; }       // s_0 = 0
    __syncthreads();
    for (int c = 1; c < N_CHUNKS; c++) {
        float ns = 0.0f;
        if (tid < AR_P)
            ns = dot64_4acc_fwd_fwd(scur, &hs[AR_P + CHUNK_L - tid]) + bv * Htail[tid];
        __syncthreads();
        if (tid < AR_P) { scur[tid] = ns; sst[c][tid] = ns; }
        __syncthreads();
    }

    // ---- ALL phi_c in parallel: phi_c[i] = sum_j Pp[i+j] * sst[c][j] ----
    if (tid < N_CHUNKS * AR_P) {
        const int c = tid >> 6;
        const int i = tid & (AR_P - 1);
        g_phi[c][i] = (c == 0) ? 0.0f : dot64_4acc_fwd_fwd(&Pp[i], sst[c]);
    }
}

// ---------------------------------------------------------------------------
// Kernel 2: fill all means. grid = 64 blocks x 256 threads.
// ---------------------------------------------------------------------------
__global__ __launch_bounds__(256) void k2_means(const float* __restrict__ bias) {
    const int c = blockIdx.x >> 3;
    const int part = blockIdx.x & 7;
    const int m0base = part * 1024;

    __shared__ __align__(16) float phi[AR_P];
    __shared__ __align__(16) float hw[1088];   // h_{m0base-64 .. m0base+1023}

    const int tid = threadIdx.x;
    if (tid < AR_P) phi[tid] = g_phi[c][tid];
    {
        const float4* g4 = reinterpret_cast<const float4*>(&g_hpad[m0base]);
        float4* s4 = reinterpret_cast<float4*>(hw);
        for (int q = tid; q < 1088 / 4; q += 256) s4[q] = g4[q];
    }
    __syncthreads();

    const float bv = bias[0];
    const int d = tid * 4;
    float a0, a1, a2, a3;
    conv4_f4(hw, 64 + d, phi, a0, a1, a2, a3);

    const int m = m0base + d;
    const float4 Hv = *reinterpret_cast<const float4*>(&g_H[m]);
    float4 r;
    r.x = fmaf(bv, Hv.x, a0);
    r.y = fmaf(bv, Hv.y, a1);
    r.z = fmaf(bv, Hv.z, a2);
    r.w = fmaf(bv, Hv.w, a3);
    *reinterpret_cast<float4*>(&g_means[c * CHUNK_L + m]) = r;
}

// ---------------------------------------------------------------------------
// Kernel 3: out[b,t] = means[t] + 0.3*noise[b,t]
// noise should now be L2-resident (prefetched during k1).
// ---------------------------------------------------------------------------
__global__ __launch_bounds__(256) void k3_out(const float4* __restrict__ noise,
                                              float4* __restrict__ out) {
    const int idx = blockIdx.x * 256 + threadIdx.x;
    const int t4 = idx & (AR_T / 4 - 1);
    const float4 nz = __ldcs(&noise[idx]);                           // L2 hit, evict-first
    const float4 mn = reinterpret_cast<const float4*>(g_means)[t4];  // L2-resident
    float4 r;
    r.x = fmaf(0.3f, nz.x, mn.x);
    r.y = fmaf(0.3f, nz.y, mn.y);
    r.z = fmaf(0.3f, nz.z, mn.z);
    r.w = fmaf(0.3f, nz.w, mn.w);
    __stcs(&out[idx], r);                                            // evict-first
}

extern "C" void kernel_launch(void* const* d_in, const int* in_sizes, int n_in,
                              void* d_out, int out_size) {
    // identify inputs by element count (params=64, bias=1, noise=256*65536)
    const float* params = nullptr;
    const float* bias   = nullptr;
    const float* noise  = nullptr;
    for (int i = 0; i < n_in; i++) {
        if (in_sizes[i] == AR_P)      params = (const float*)d_in[i];
        else if (in_sizes[i] == 1)    bias   = (const float*)d_in[i];
        else                          noise  = (const float*)d_in[i];
    }

    k1_prep<<<K1_GRID, 1024>>>(params, bias, (const float4*)noise);
    k2_means<<<N_CHUNKS * 8, 256>>>(bias);

    const int total4 = out_size / 4;          // 4,194,304 float4s
    k3_out<<<total4 / 256, 256>>>((const float4*)noise, (float4*)d_out);
}